// round 9
// baseline (speedup 1.0000x reference)
#include <cuda_runtime.h>
#include <cuda_bf16.h>

#define BATCH 4
#define NTOK 2048
#define DM 512
#define NH 8
#define HD 64
#define MROWS (BATCH * NTOK)   // 8192

// ---------------- scratch (device globals; no allocations allowed) ----------
__device__ unsigned short g_xhi [MROWS * DM];
__device__ unsigned short g_xlo [MROWS * DM];
__device__ unsigned short g_qhi [MROWS * DM];
__device__ unsigned short g_qlo [MROWS * DM];
__device__ unsigned short g_khi [MROWS * DM];
__device__ unsigned short g_klo [MROWS * DM];
__device__ unsigned short g_vthi[MROWS * DM];   // V^T bf16 [b][h][d][n]
__device__ unsigned short g_vtlo[MROWS * DM];
__device__ unsigned short g_aohi[MROWS * DM];
__device__ unsigned short g_aolo[MROWS * DM];
__device__ unsigned short g_wthi[4 * DM * DM];  // W^T [which][n][k]
__device__ unsigned short g_wtlo[4 * DM * DM];
__device__ unsigned long long g_adjbits[NTOK * (NTOK / 64)];  // [row][word]

// ---------------- helpers ---------------------------------------------------
__device__ __forceinline__ unsigned packbf(float lo, float hi) {
    unsigned r;
    asm("cvt.rn.bf16x2.f32 %0, %1, %2;" : "=r"(r) : "f"(hi), "f"(lo));
    return r;  // low 16 bits = bf16(lo), high 16 = bf16(hi)
}

__device__ __forceinline__ void split2(float v0, float v1, unsigned& h, unsigned& l) {
    h = packbf(v0, v1);
    float r0 = v0 - __uint_as_float(h << 16);
    float r1 = v1 - __uint_as_float(h & 0xFFFF0000u);
    l = packbf(r0, r1);
}

__device__ __forceinline__ void mma16816(float* c,
                                         unsigned a0, unsigned a1, unsigned a2, unsigned a3,
                                         unsigned b0, unsigned b1) {
    asm volatile(
        "mma.sync.aligned.m16n8k16.row.col.f32.bf16.bf16.f32 "
        "{%0,%1,%2,%3}, {%4,%5,%6,%7}, {%8,%9}, {%0,%1,%2,%3};"
        : "+f"(c[0]), "+f"(c[1]), "+f"(c[2]), "+f"(c[3])
        : "r"(a0), "r"(a1), "r"(a2), "r"(a3), "r"(b0), "r"(b1));
}

// ---------------------------------------------------------------------------
// split_x: fp32 -> bf16 hi/lo
// ---------------------------------------------------------------------------
__global__ __launch_bounds__(256)
void split_x_kernel(const float* __restrict__ X) {
    size_t i = ((size_t)blockIdx.x * 256 + threadIdx.x) * 4;
    float4 v = *(const float4*)(X + i);
    unsigned h01, l01, h23, l23;
    split2(v.x, v.y, h01, l01);
    split2(v.z, v.w, h23, l23);
    *(uint2*)(g_xhi + i) = make_uint2(h01, h23);
    *(uint2*)(g_xlo + i) = make_uint2(l01, l23);
}

// ---------------------------------------------------------------------------
// split_wT: W [k][n] fp32 -> W^T [n][k] bf16 hi/lo (into slot `which`)
// ---------------------------------------------------------------------------
__global__ __launch_bounds__(256)
void split_wT_kernel(const float* __restrict__ W, int which) {
    __shared__ float S[32][33];
    const int nb = blockIdx.x * 32, kb = blockIdx.y * 32;
    const int c = threadIdx.x & 31, r8 = threadIdx.x >> 5;
    #pragma unroll
    for (int i = 0; i < 4; i++) {
        int r = r8 + i * 8;
        S[r][c] = W[(size_t)(kb + r) * DM + nb + c];
    }
    __syncthreads();
    unsigned short* Thi = g_wthi + (size_t)which * DM * DM;
    unsigned short* Tlo = g_wtlo + (size_t)which * DM * DM;
    #pragma unroll
    for (int i = 0; i < 4; i++) {
        int n = r8 + i * 8;
        float v = S[c][n];
        __nv_bfloat16 hb = __float2bfloat16(v);
        float hv = __bfloat162float(hb);
        __nv_bfloat16 lb = __float2bfloat16(v - hv);
        size_t off = (size_t)(nb + n) * DM + kb + c;
        Thi[off] = *(unsigned short*)&hb;
        Tlo[off] = *(unsigned short*)&lb;
    }
}

// ---------------------------------------------------------------------------
// pack_adj: adj fp32 [N][N] -> u64 bitmask per 64-key word (one warp per word)
// ---------------------------------------------------------------------------
__global__ __launch_bounds__(256)
void pack_adj_kernel(const float* __restrict__ adj) {
    int word = blockIdx.x * 8 + (threadIdx.x >> 5);
    int lane = threadIdx.x & 31;
    int row = word >> 5;            // NTOK/64 = 32 words per row
    int j   = word & 31;
    const float* p = adj + (size_t)row * NTOK + j * 64;
    unsigned lo = __ballot_sync(0xffffffffu, p[lane] != 0.0f);
    unsigned hi = __ballot_sync(0xffffffffu, p[lane + 32] != 0.0f);
    g_adjbits[word] = ((unsigned long long)hi << 32) | lo;
}

// ---------------------------------------------------------------------------
// bf16-split MMA GEMM (unchanged from R8):  C[8192,512] = A @ W^T + bias
// ---------------------------------------------------------------------------
#define GA_HI 0
#define GA_LO 4608
#define GB_HI 9216
#define GB_LO 11520
#define GEMM_SMEM_BYTES (13824 * 4)

template <int MODE>
__global__ __launch_bounds__(256)
void mma_gemm_kernel(const unsigned short* __restrict__ Ahi,
                     const unsigned short* __restrict__ Alo,
                     const unsigned short* __restrict__ Bhi,
                     const unsigned short* __restrict__ Blo,
                     const float* __restrict__ bias,
                     float* __restrict__ Cf,
                     unsigned short* __restrict__ Chi,
                     unsigned short* __restrict__ Clo) {
    extern __shared__ unsigned sw[];

    const int nb = blockIdx.x * 64;
    const int mb = blockIdx.y * 128;
    const int tid = threadIdx.x;
    const int wid = tid >> 5, lane = tid & 31;
    const int wm = wid >> 1, wn = wid & 1;
    const int qr = lane >> 2, qc = lane & 3;

    float acc[2][4][4];
    #pragma unroll
    for (int mf = 0; mf < 2; mf++)
        #pragma unroll
        for (int nf = 0; nf < 4; nf++)
            #pragma unroll
            for (int j = 0; j < 4; j++) acc[mf][nf][j] = 0.0f;

    for (int k0 = 0; k0 < DM; k0 += 64) {
        __syncthreads();
        #pragma unroll
        for (int t = tid; t < 1024; t += 256) {
            int r = t >> 3, s = t & 7;
            size_t g = (size_t)(mb + r) * DM + k0 + s * 8;
            *(uint4*)&sw[GA_HI + r * 36 + s * 4] = *(const uint4*)(Ahi + g);
            *(uint4*)&sw[GA_LO + r * 36 + s * 4] = *(const uint4*)(Alo + g);
        }
        #pragma unroll
        for (int t = tid; t < 512; t += 256) {
            int r = t >> 3, s = t & 7;
            size_t g = (size_t)(nb + r) * DM + k0 + s * 8;
            *(uint4*)&sw[GB_HI + r * 36 + s * 4] = *(const uint4*)(Bhi + g);
            *(uint4*)&sw[GB_LO + r * 36 + s * 4] = *(const uint4*)(Blo + g);
        }
        __syncthreads();

        #pragma unroll
        for (int ks = 0; ks < 4; ks++) {
            unsigned ah[2][4], al[2][4];
            #pragma unroll
            for (int mf = 0; mf < 2; mf++) {
                int ab = (wm * 32 + mf * 16 + qr) * 36 + ks * 8 + qc;
                ah[mf][0] = sw[GA_HI + ab];
                ah[mf][1] = sw[GA_HI + ab + 8 * 36];
                ah[mf][2] = sw[GA_HI + ab + 4];
                ah[mf][3] = sw[GA_HI + ab + 8 * 36 + 4];
                al[mf][0] = sw[GA_LO + ab];
                al[mf][1] = sw[GA_LO + ab + 8 * 36];
                al[mf][2] = sw[GA_LO + ab + 4];
                al[mf][3] = sw[GA_LO + ab + 8 * 36 + 4];
            }
            #pragma unroll
            for (int nf = 0; nf < 4; nf++) {
                int bb = (wn * 32 + nf * 8 + qr) * 36 + ks * 8 + qc;
                unsigned bh0 = sw[GB_HI + bb], bh1 = sw[GB_HI + bb + 4];
                unsigned bl0 = sw[GB_LO + bb], bl1 = sw[GB_LO + bb + 4];
                #pragma unroll
                for (int mf = 0; mf < 2; mf++) {
                    mma16816(acc[mf][nf], ah[mf][0], ah[mf][1], ah[mf][2], ah[mf][3], bh0, bh1);
                    mma16816(acc[mf][nf], ah[mf][0], ah[mf][1], ah[mf][2], ah[mf][3], bl0, bl1);
                    mma16816(acc[mf][nf], al[mf][0], al[mf][1], al[mf][2], al[mf][3], bh0, bh1);
                }
            }
        }
    }

    if (MODE == 0 || MODE == 1) {
        #pragma unroll
        for (int mf = 0; mf < 2; mf++) {
            #pragma unroll
            for (int nf = 0; nf < 4; nf++) {
                int col = wn * 32 + nf * 8 + qc * 2;
                float2 bi = *(const float2*)(bias + nb + col);
                int r0 = mb + wm * 32 + mf * 16 + qr;
                float v0 = acc[mf][nf][0] + bi.x;
                float v1 = acc[mf][nf][1] + bi.y;
                float v2 = acc[mf][nf][2] + bi.x;
                float v3 = acc[mf][nf][3] + bi.y;
                if (MODE == 0) {
                    *(float2*)(Cf + (size_t)r0 * DM + nb + col) = make_float2(v0, v1);
                    *(float2*)(Cf + (size_t)(r0 + 8) * DM + nb + col) = make_float2(v2, v3);
                } else {
                    unsigned h, l;
                    split2(v0, v1, h, l);
                    *(unsigned*)(Chi + (size_t)r0 * DM + nb + col) = h;
                    *(unsigned*)(Clo + (size_t)r0 * DM + nb + col) = l;
                    split2(v2, v3, h, l);
                    *(unsigned*)(Chi + (size_t)(r0 + 8) * DM + nb + col) = h;
                    *(unsigned*)(Clo + (size_t)(r0 + 8) * DM + nb + col) = l;
                }
            }
        }
    } else {
        __syncthreads();
        float* T = (float*)sw;  // T[d][token], stride 132
        #pragma unroll
        for (int mf = 0; mf < 2; mf++) {
            #pragma unroll
            for (int nf = 0; nf < 4; nf++) {
                int c = wn * 32 + nf * 8 + qc * 2;
                float2 bi = *(const float2*)(bias + nb + c);
                int r = wm * 32 + mf * 16 + qr;
                T[(c + 0) * 132 + r]     = acc[mf][nf][0] + bi.x;
                T[(c + 1) * 132 + r]     = acc[mf][nf][1] + bi.y;
                T[(c + 0) * 132 + r + 8] = acc[mf][nf][2] + bi.x;
                T[(c + 1) * 132 + r + 8] = acc[mf][nf][3] + bi.y;
            }
        }
        __syncthreads();
        const int b  = mb >> 11;
        const int n0 = mb & (NTOK - 1);
        const int h  = nb >> 6;
        #pragma unroll
        for (int t = tid; t < 2048; t += 256) {
            int dl = t >> 5;
            int r4 = (t & 31) * 4;
            float v0 = T[dl * 132 + r4 + 0];
            float v1 = T[dl * 132 + r4 + 1];
            float v2 = T[dl * 132 + r4 + 2];
            float v3 = T[dl * 132 + r4 + 3];
            unsigned h01, l01, h23, l23;
            split2(v0, v1, h01, l01);
            split2(v2, v3, h23, l23);
            size_t off = ((size_t)((b * NH + h) * HD + dl)) * NTOK + n0 + r4;
            *(uint2*)(Chi + off) = make_uint2(h01, h23);
            *(uint2*)(Clo + off) = make_uint2(l01, l23);
        }
    }
}

// ---------------------------------------------------------------------------
// Attention v2: q-tile 128 (4 warps x 32 rows), k-tile 64, no-max softmax,
// bitmask adjacency. smem words (stride 36):
//   Qhi[128*36] Qlo[128*36] Khi[64*36] Klo[64*36] Vhi[64*36] Vlo[64*36]
// ---------------------------------------------------------------------------
#define AQ_HI 0
#define AQ_LO 4608
#define AK_HI 9216
#define AK_LO 11520
#define AV_HI 13824
#define AV_LO 16128
#define ATTN_SMEM_BYTES (18432 * 4)

__global__ __launch_bounds__(128)
void attn_mma_kernel() {
    extern __shared__ unsigned smw[];

    const int qt = blockIdx.x;
    const int h  = blockIdx.y;
    const int b  = blockIdx.z;
    const int tid  = threadIdx.x;
    const int wid  = tid >> 5;
    const int lane = tid & 31;
    const int qbase = qt * 128;
    const int qr = lane >> 2;
    const int qc = lane & 3;

    // ---- load Q tile (128 rows, hi/lo) ----
    for (int t = tid; t < 1024; t += 128) {
        int r = t >> 3, s = t & 7;
        size_t g = (size_t)(b * NTOK + qbase + r) * DM + h * HD + s * 8;
        *(uint4*)&smw[AQ_HI + r * 36 + s * 4] = *(const uint4*)(g_qhi + g);
        *(uint4*)&smw[AQ_LO + r * 36 + s * 4] = *(const uint4*)(g_qlo + g);
    }

    float oacc[2][8][4];
    float lacc[2][2];
    #pragma unroll
    for (int mf = 0; mf < 2; mf++) {
        lacc[mf][0] = 0.0f; lacc[mf][1] = 0.0f;
        #pragma unroll
        for (int nt = 0; nt < 8; nt++)
            #pragma unroll
            for (int j = 0; j < 4; j++) oacc[mf][nt][j] = 0.0f;
    }

    const int rowA0 = qbase + wid * 32 + qr;           // mf=0 row A
    const unsigned long long* bitsrow = g_adjbits;

    for (int kt = 0; kt < NTOK / 64; kt++) {
        const int kbase = kt * 64;
        __syncthreads();
        for (int t = tid; t < 512; t += 128) {
            int r = t >> 3, s = t & 7;
            size_t gk = (size_t)(b * NTOK + kbase + r) * DM + h * HD + s * 8;
            *(uint4*)&smw[AK_HI + r * 36 + s * 4] = *(const uint4*)(g_khi + gk);
            *(uint4*)&smw[AK_LO + r * 36 + s * 4] = *(const uint4*)(g_klo + gk);
            size_t gv = ((size_t)((b * NH + h) * HD + r)) * NTOK + kbase + s * 8;
            *(uint4*)&smw[AV_HI + r * 36 + s * 4] = *(const uint4*)(g_vthi + gv);
            *(uint4*)&smw[AV_LO + r * 36 + s * 4] = *(const uint4*)(g_vtlo + gv);
        }
        __syncthreads();

        // ---- S = Q @ K^T ----
        float s_[2][8][4];
        #pragma unroll
        for (int mf = 0; mf < 2; mf++)
            #pragma unroll
            for (int nt = 0; nt < 8; nt++)
                #pragma unroll
                for (int j = 0; j < 4; j++) s_[mf][nt][j] = 0.0f;

        #pragma unroll
        for (int kc = 0; kc < 4; kc++) {
            unsigned ah[2][4], al[2][4];
            #pragma unroll
            for (int mf = 0; mf < 2; mf++) {
                int ab = (wid * 32 + mf * 16 + qr) * 36 + kc * 8 + qc;
                ah[mf][0] = smw[AQ_HI + ab];
                ah[mf][1] = smw[AQ_HI + ab + 8 * 36];
                ah[mf][2] = smw[AQ_HI + ab + 4];
                ah[mf][3] = smw[AQ_HI + ab + 8 * 36 + 4];
                al[mf][0] = smw[AQ_LO + ab];
                al[mf][1] = smw[AQ_LO + ab + 8 * 36];
                al[mf][2] = smw[AQ_LO + ab + 4];
                al[mf][3] = smw[AQ_LO + ab + 8 * 36 + 4];
            }
            #pragma unroll
            for (int nt = 0; nt < 8; nt++) {
                const int bb = (nt * 8 + qr) * 36 + kc * 8 + qc;
                unsigned bh0 = smw[AK_HI + bb];
                unsigned bh1 = smw[AK_HI + bb + 4];
                unsigned bl0 = smw[AK_LO + bb];
                unsigned bl1 = smw[AK_LO + bb + 4];
                #pragma unroll
                for (int mf = 0; mf < 2; mf++) {
                    mma16816(s_[mf][nt], ah[mf][0], ah[mf][1], ah[mf][2], ah[mf][3], bh0, bh1);
                    mma16816(s_[mf][nt], ah[mf][0], ah[mf][1], ah[mf][2], ah[mf][3], bl0, bl1);
                    mma16816(s_[mf][nt], al[mf][0], al[mf][1], al[mf][2], al[mf][3], bh0, bh1);
                }
            }
        }

        // ---- no-max softmax: P = expf(s/8) * maskbit ----
        #pragma unroll
        for (int mf = 0; mf < 2; mf++) {
            unsigned long long bA = bitsrow[(size_t)(rowA0 + mf * 16) * 32 + kt];
            unsigned long long bB = bitsrow[(size_t)(rowA0 + mf * 16 + 8) * 32 + kt];
            float rsA = 0.0f, rsB = 0.0f;
            #pragma unroll
            for (int nt = 0; nt < 8; nt++) {
                int sh = nt * 8 + qc * 2;
                float mA0 = (float)((bA >> sh) & 1ull);
                float mA1 = (float)((bA >> (sh + 1)) & 1ull);
                float mB0 = (float)((bB >> sh) & 1ull);
                float mB1 = (float)((bB >> (sh + 1)) & 1ull);
                s_[mf][nt][0] = __expf(s_[mf][nt][0] * 0.125f) * mA0;
                s_[mf][nt][1] = __expf(s_[mf][nt][1] * 0.125f) * mA1;
                s_[mf][nt][2] = __expf(s_[mf][nt][2] * 0.125f) * mB0;
                s_[mf][nt][3] = __expf(s_[mf][nt][3] * 0.125f) * mB1;
                rsA += s_[mf][nt][0] + s_[mf][nt][1];
                rsB += s_[mf][nt][2] + s_[mf][nt][3];
            }
            lacc[mf][0] += rsA;
            lacc[mf][1] += rsB;
        }

        // ---- O += P @ V ----
        #pragma unroll
        for (int kc = 0; kc < 4; kc++) {
            unsigned ph[2][4], pl[2][4];
            #pragma unroll
            for (int mf = 0; mf < 2; mf++) {
                const int n0 = 2 * kc, n1 = 2 * kc + 1;
                split2(s_[mf][n0][0], s_[mf][n0][1], ph[mf][0], pl[mf][0]);
                split2(s_[mf][n0][2], s_[mf][n0][3], ph[mf][1], pl[mf][1]);
                split2(s_[mf][n1][0], s_[mf][n1][1], ph[mf][2], pl[mf][2]);
                split2(s_[mf][n1][2], s_[mf][n1][3], ph[mf][3], pl[mf][3]);
            }
            #pragma unroll
            for (int nt = 0; nt < 8; nt++) {
                const int bb = (nt * 8 + qr) * 36 + kc * 8 + qc;
                unsigned bh0 = smw[AV_HI + bb];
                unsigned bh1 = smw[AV_HI + bb + 4];
                unsigned bl0 = smw[AV_LO + bb];
                unsigned bl1 = smw[AV_LO + bb + 4];
                #pragma unroll
                for (int mf = 0; mf < 2; mf++) {
                    mma16816(oacc[mf][nt], ph[mf][0], ph[mf][1], ph[mf][2], ph[mf][3], bh0, bh1);
                    mma16816(oacc[mf][nt], ph[mf][0], ph[mf][1], ph[mf][2], ph[mf][3], bl0, bl1);
                    mma16816(oacc[mf][nt], pl[mf][0], pl[mf][1], pl[mf][2], pl[mf][3], bh0, bh1);
                }
            }
        }
    }

    // ---- epilogue: reduce l across qc lanes, normalize, split-store AO ----
    #pragma unroll
    for (int mf = 0; mf < 2; mf++) {
        float lA = lacc[mf][0], lB = lacc[mf][1];
        lA += __shfl_xor_sync(0xffffffffu, lA, 1);
        lA += __shfl_xor_sync(0xffffffffu, lA, 2);
        lB += __shfl_xor_sync(0xffffffffu, lB, 1);
        lB += __shfl_xor_sync(0xffffffffu, lB, 2);
        float invA = 1.0f / lA;
        float invB = 1.0f / lB;
        size_t offA = (size_t)(b * NTOK + rowA0 + mf * 16) * DM + h * HD;
        size_t offB = offA + (size_t)8 * DM;
        #pragma unroll
        for (int nt = 0; nt < 8; nt++) {
            int col = nt * 8 + qc * 2;
            unsigned hA, lAv, hB, lBv;
            split2(oacc[mf][nt][0] * invA, oacc[mf][nt][1] * invA, hA, lAv);
            split2(oacc[mf][nt][2] * invB, oacc[mf][nt][3] * invB, hB, lBv);
            *(unsigned*)(g_aohi + offA + col) = hA;
            *(unsigned*)(g_aolo + offA + col) = lAv;
            *(unsigned*)(g_aohi + offB + col) = hB;
            *(unsigned*)(g_aolo + offB + col) = lBv;
        }
    }
}

// ---------------------------------------------------------------------------
extern "C" void kernel_launch(void* const* d_in, const int* in_sizes, int n_in,
                              void* d_out, int out_size) {
    const float* x   = (const float*)d_in[0];
    const float* adj = (const float*)d_in[1];
    const float* Wq  = (const float*)d_in[2];
    const float* bq  = (const float*)d_in[3];
    const float* Wk  = (const float*)d_in[4];
    const float* bk  = (const float*)d_in[5];
    const float* Wv  = (const float*)d_in[6];
    const float* bv  = (const float*)d_in[7];
    const float* Wo  = (const float*)d_in[8];
    const float* bo  = (const float*)d_in[9];
    float* out = (float*)d_out;

    unsigned short *xhi, *xlo, *qhi, *qlo, *khi, *klo, *vthi, *vtlo, *aohi, *aolo, *wthi, *wtlo;
    cudaGetSymbolAddress((void**)&xhi,  g_xhi);
    cudaGetSymbolAddress((void**)&xlo,  g_xlo);
    cudaGetSymbolAddress((void**)&qhi,  g_qhi);
    cudaGetSymbolAddress((void**)&qlo,  g_qlo);
    cudaGetSymbolAddress((void**)&khi,  g_khi);
    cudaGetSymbolAddress((void**)&klo,  g_klo);
    cudaGetSymbolAddress((void**)&vthi, g_vthi);
    cudaGetSymbolAddress((void**)&vtlo, g_vtlo);
    cudaGetSymbolAddress((void**)&aohi, g_aohi);
    cudaGetSymbolAddress((void**)&aolo, g_aolo);
    cudaGetSymbolAddress((void**)&wthi, g_wthi);
    cudaGetSymbolAddress((void**)&wtlo, g_wtlo);

    // 1) split inputs / weights / pack mask
    split_x_kernel<<<(MROWS * DM) / (256 * 4), 256>>>(x);
    dim3 wg(DM / 32, DM / 32);
    split_wT_kernel<<<wg, 256>>>(Wq, 0);
    split_wT_kernel<<<wg, 256>>>(Wk, 1);
    split_wT_kernel<<<wg, 256>>>(Wv, 2);
    split_wT_kernel<<<wg, 256>>>(Wo, 3);
    pack_adj_kernel<<<(NTOK * (NTOK / 64)) / 8, 256>>>(adj);

    // 2) projection GEMMs
    cudaFuncSetAttribute(mma_gemm_kernel<0>, cudaFuncAttributeMaxDynamicSharedMemorySize, GEMM_SMEM_BYTES);
    cudaFuncSetAttribute(mma_gemm_kernel<1>, cudaFuncAttributeMaxDynamicSharedMemorySize, GEMM_SMEM_BYTES);
    cudaFuncSetAttribute(mma_gemm_kernel<2>, cudaFuncAttributeMaxDynamicSharedMemorySize, GEMM_SMEM_BYTES);
    dim3 gg(DM / 64, MROWS / 128);
    mma_gemm_kernel<1><<<gg, 256, GEMM_SMEM_BYTES>>>(xhi, xlo, wthi + 0 * DM * DM, wtlo + 0 * DM * DM,
                                                     bq, nullptr, qhi, qlo);
    mma_gemm_kernel<1><<<gg, 256, GEMM_SMEM_BYTES>>>(xhi, xlo, wthi + 1 * DM * DM, wtlo + 1 * DM * DM,
                                                     bk, nullptr, khi, klo);
    mma_gemm_kernel<2><<<gg, 256, GEMM_SMEM_BYTES>>>(xhi, xlo, wthi + 2 * DM * DM, wtlo + 2 * DM * DM,
                                                     bv, nullptr, vthi, vtlo);

    // 3) attention (q-tile 128)
    cudaFuncSetAttribute(attn_mma_kernel, cudaFuncAttributeMaxDynamicSharedMemorySize, ATTN_SMEM_BYTES);
    attn_mma_kernel<<<dim3(NTOK / 128, NH, BATCH), 128, ATTN_SMEM_BYTES>>>();

    // 4) output projection
    mma_gemm_kernel<0><<<gg, 256, GEMM_SMEM_BYTES>>>(aohi, aolo, wthi + 3 * DM * DM, wtlo + 3 * DM * DM,
                                                     bo, out, nullptr, nullptr);
}

// round 11
// speedup vs baseline: 1.1438x; 1.1438x over previous
#include <cuda_runtime.h>
#include <cuda_bf16.h>

#define BATCH 4
#define NTOK 2048
#define DM 512
#define NH 8
#define HD 64
#define MROWS (BATCH * NTOK)   // 8192

// ---------------- scratch (device globals; no allocations allowed) ----------
__device__ unsigned short g_xhi [MROWS * DM];
__device__ unsigned short g_xlo [MROWS * DM];
__device__ unsigned short g_qhi [MROWS * DM];
__device__ unsigned short g_qlo [MROWS * DM];
__device__ unsigned short g_khi [MROWS * DM];
__device__ unsigned short g_klo [MROWS * DM];
__device__ unsigned short g_vthi[MROWS * DM];   // V^T bf16 [b][h][d][n]
__device__ unsigned short g_vtlo[MROWS * DM];
__device__ unsigned short g_aohi[MROWS * DM];
__device__ unsigned short g_aolo[MROWS * DM];
__device__ unsigned short g_wthi[4 * DM * DM];  // W^T [which][n][k]
__device__ unsigned short g_wtlo[4 * DM * DM];
__device__ unsigned long long g_adjbits[NTOK * (NTOK / 64)];  // [row][word]

// ---------------- helpers ---------------------------------------------------
__device__ __forceinline__ unsigned packbf(float lo, float hi) {
    unsigned r;
    asm("cvt.rn.bf16x2.f32 %0, %1, %2;" : "=r"(r) : "f"(hi), "f"(lo));
    return r;  // low 16 bits = bf16(lo), high 16 = bf16(hi)
}

__device__ __forceinline__ void split2(float v0, float v1, unsigned& h, unsigned& l) {
    h = packbf(v0, v1);
    float r0 = v0 - __uint_as_float(h << 16);
    float r1 = v1 - __uint_as_float(h & 0xFFFF0000u);
    l = packbf(r0, r1);
}

__device__ __forceinline__ void mma16816(float* c,
                                         unsigned a0, unsigned a1, unsigned a2, unsigned a3,
                                         unsigned b0, unsigned b1) {
    asm volatile(
        "mma.sync.aligned.m16n8k16.row.col.f32.bf16.bf16.f32 "
        "{%0,%1,%2,%3}, {%4,%5,%6,%7}, {%8,%9}, {%0,%1,%2,%3};"
        : "+f"(c[0]), "+f"(c[1]), "+f"(c[2]), "+f"(c[3])
        : "r"(a0), "r"(a1), "r"(a2), "r"(a3), "r"(b0), "r"(b1));
}

// ---------------------------------------------------------------------------
// split_x: fp32 -> bf16 hi/lo
// ---------------------------------------------------------------------------
__global__ __launch_bounds__(256)
void split_x_kernel(const float* __restrict__ X) {
    size_t i = ((size_t)blockIdx.x * 256 + threadIdx.x) * 4;
    float4 v = *(const float4*)(X + i);
    unsigned h01, l01, h23, l23;
    split2(v.x, v.y, h01, l01);
    split2(v.z, v.w, h23, l23);
    *(uint2*)(g_xhi + i) = make_uint2(h01, h23);
    *(uint2*)(g_xlo + i) = make_uint2(l01, l23);
}

// ---------------------------------------------------------------------------
// split_wT: W [k][n] fp32 -> W^T [n][k] bf16 hi/lo (into slot `which`)
// ---------------------------------------------------------------------------
__global__ __launch_bounds__(256)
void split_wT_kernel(const float* __restrict__ W, int which) {
    __shared__ float S[32][33];
    const int nb = blockIdx.x * 32, kb = blockIdx.y * 32;
    const int c = threadIdx.x & 31, r8 = threadIdx.x >> 5;
    #pragma unroll
    for (int i = 0; i < 4; i++) {
        int r = r8 + i * 8;
        S[r][c] = W[(size_t)(kb + r) * DM + nb + c];
    }
    __syncthreads();
    unsigned short* Thi = g_wthi + (size_t)which * DM * DM;
    unsigned short* Tlo = g_wtlo + (size_t)which * DM * DM;
    #pragma unroll
    for (int i = 0; i < 4; i++) {
        int n = r8 + i * 8;
        float v = S[c][n];
        __nv_bfloat16 hb = __float2bfloat16(v);
        float hv = __bfloat162float(hb);
        __nv_bfloat16 lb = __float2bfloat16(v - hv);
        size_t off = (size_t)(nb + n) * DM + kb + c;
        Thi[off] = *(unsigned short*)&hb;
        Tlo[off] = *(unsigned short*)&lb;
    }
}

// ---------------------------------------------------------------------------
// pack_adj: adj fp32 [N][N] -> u64 bitmask per 64-key word (one warp per word)
// ---------------------------------------------------------------------------
__global__ __launch_bounds__(256)
void pack_adj_kernel(const float* __restrict__ adj) {
    int word = blockIdx.x * 8 + (threadIdx.x >> 5);
    int lane = threadIdx.x & 31;
    int row = word >> 5;            // NTOK/64 = 32 words per row
    int j   = word & 31;
    const float* p = adj + (size_t)row * NTOK + j * 64;
    unsigned lo = __ballot_sync(0xffffffffu, p[lane] != 0.0f);
    unsigned hi = __ballot_sync(0xffffffffu, p[lane + 32] != 0.0f);
    g_adjbits[word] = ((unsigned long long)hi << 32) | lo;
}

// ---------------------------------------------------------------------------
// bf16-split MMA GEMM:  C[8192,512] = A @ W^T + bias
// Tile 128(M) x 64(N), BK=64, 8 warps, warp tile 32x32.
// MODE 0: fp32 out, MODE 1: split out (Q,K), MODE 2: transposed split out (V)
// ---------------------------------------------------------------------------
#define GA_HI 0
#define GA_LO 4608
#define GB_HI 9216
#define GB_LO 11520
#define GEMM_SMEM_BYTES (13824 * 4)

template <int MODE>
__global__ __launch_bounds__(256)
void mma_gemm_kernel(const unsigned short* __restrict__ Ahi,
                     const unsigned short* __restrict__ Alo,
                     const unsigned short* __restrict__ Bhi,
                     const unsigned short* __restrict__ Blo,
                     const float* __restrict__ bias,
                     float* __restrict__ Cf,
                     unsigned short* __restrict__ Chi,
                     unsigned short* __restrict__ Clo) {
    extern __shared__ unsigned sw[];

    const int nb = blockIdx.x * 64;
    const int mb = blockIdx.y * 128;
    const int tid = threadIdx.x;
    const int wid = tid >> 5, lane = tid & 31;
    const int wm = wid >> 1, wn = wid & 1;
    const int qr = lane >> 2, qc = lane & 3;

    float acc[2][4][4];
    #pragma unroll
    for (int mf = 0; mf < 2; mf++)
        #pragma unroll
        for (int nf = 0; nf < 4; nf++)
            #pragma unroll
            for (int j = 0; j < 4; j++) acc[mf][nf][j] = 0.0f;

    for (int k0 = 0; k0 < DM; k0 += 64) {
        __syncthreads();
        #pragma unroll
        for (int t = tid; t < 1024; t += 256) {
            int r = t >> 3, s = t & 7;
            size_t g = (size_t)(mb + r) * DM + k0 + s * 8;
            *(uint4*)&sw[GA_HI + r * 36 + s * 4] = *(const uint4*)(Ahi + g);
            *(uint4*)&sw[GA_LO + r * 36 + s * 4] = *(const uint4*)(Alo + g);
        }
        #pragma unroll
        for (int t = tid; t < 512; t += 256) {
            int r = t >> 3, s = t & 7;
            size_t g = (size_t)(nb + r) * DM + k0 + s * 8;
            *(uint4*)&sw[GB_HI + r * 36 + s * 4] = *(const uint4*)(Bhi + g);
            *(uint4*)&sw[GB_LO + r * 36 + s * 4] = *(const uint4*)(Blo + g);
        }
        __syncthreads();

        #pragma unroll
        for (int ks = 0; ks < 4; ks++) {
            unsigned ah[2][4], al[2][4];
            #pragma unroll
            for (int mf = 0; mf < 2; mf++) {
                int ab = (wm * 32 + mf * 16 + qr) * 36 + ks * 8 + qc;
                ah[mf][0] = sw[GA_HI + ab];
                ah[mf][1] = sw[GA_HI + ab + 8 * 36];
                ah[mf][2] = sw[GA_HI + ab + 4];
                ah[mf][3] = sw[GA_HI + ab + 8 * 36 + 4];
                al[mf][0] = sw[GA_LO + ab];
                al[mf][1] = sw[GA_LO + ab + 8 * 36];
                al[mf][2] = sw[GA_LO + ab + 4];
                al[mf][3] = sw[GA_LO + ab + 8 * 36 + 4];
            }
            #pragma unroll
            for (int nf = 0; nf < 4; nf++) {
                int bb = (wn * 32 + nf * 8 + qr) * 36 + ks * 8 + qc;
                unsigned bh0 = sw[GB_HI + bb], bh1 = sw[GB_HI + bb + 4];
                unsigned bl0 = sw[GB_LO + bb], bl1 = sw[GB_LO + bb + 4];
                #pragma unroll
                for (int mf = 0; mf < 2; mf++) {
                    mma16816(acc[mf][nf], ah[mf][0], ah[mf][1], ah[mf][2], ah[mf][3], bh0, bh1);
                    mma16816(acc[mf][nf], ah[mf][0], ah[mf][1], ah[mf][2], ah[mf][3], bl0, bl1);
                    mma16816(acc[mf][nf], al[mf][0], al[mf][1], al[mf][2], al[mf][3], bh0, bh1);
                }
            }
        }
    }

    if (MODE == 0 || MODE == 1) {
        #pragma unroll
        for (int mf = 0; mf < 2; mf++) {
            #pragma unroll
            for (int nf = 0; nf < 4; nf++) {
                int col = wn * 32 + nf * 8 + qc * 2;
                float2 bi = *(const float2*)(bias + nb + col);
                int r0 = mb + wm * 32 + mf * 16 + qr;
                float v0 = acc[mf][nf][0] + bi.x;
                float v1 = acc[mf][nf][1] + bi.y;
                float v2 = acc[mf][nf][2] + bi.x;
                float v3 = acc[mf][nf][3] + bi.y;
                if (MODE == 0) {
                    *(float2*)(Cf + (size_t)r0 * DM + nb + col) = make_float2(v0, v1);
                    *(float2*)(Cf + (size_t)(r0 + 8) * DM + nb + col) = make_float2(v2, v3);
                } else {
                    unsigned h, l;
                    split2(v0, v1, h, l);
                    *(unsigned*)(Chi + (size_t)r0 * DM + nb + col) = h;
                    *(unsigned*)(Clo + (size_t)r0 * DM + nb + col) = l;
                    split2(v2, v3, h, l);
                    *(unsigned*)(Chi + (size_t)(r0 + 8) * DM + nb + col) = h;
                    *(unsigned*)(Clo + (size_t)(r0 + 8) * DM + nb + col) = l;
                }
            }
        }
    } else {
        __syncthreads();
        float* T = (float*)sw;  // T[d][token], stride 132
        #pragma unroll
        for (int mf = 0; mf < 2; mf++) {
            #pragma unroll
            for (int nf = 0; nf < 4; nf++) {
                int c = wn * 32 + nf * 8 + qc * 2;
                float2 bi = *(const float2*)(bias + nb + c);
                int r = wm * 32 + mf * 16 + qr;
                T[(c + 0) * 132 + r]     = acc[mf][nf][0] + bi.x;
                T[(c + 1) * 132 + r]     = acc[mf][nf][1] + bi.y;
                T[(c + 0) * 132 + r + 8] = acc[mf][nf][2] + bi.x;
                T[(c + 1) * 132 + r + 8] = acc[mf][nf][3] + bi.y;
            }
        }
        __syncthreads();
        const int b  = mb >> 11;
        const int n0 = mb & (NTOK - 1);
        const int h  = nb >> 6;
        #pragma unroll
        for (int t = tid; t < 2048; t += 256) {
            int dl = t >> 5;
            int r4 = (t & 31) * 4;
            float v0 = T[dl * 132 + r4 + 0];
            float v1 = T[dl * 132 + r4 + 1];
            float v2 = T[dl * 132 + r4 + 2];
            float v3 = T[dl * 132 + r4 + 3];
            unsigned h01, l01, h23, l23;
            split2(v0, v1, h01, l01);
            split2(v2, v3, h23, l23);
            size_t off = ((size_t)((b * NH + h) * HD + dl)) * NTOK + n0 + r4;
            *(uint2*)(Chi + off) = make_uint2(h01, h23);
            *(uint2*)(Clo + off) = make_uint2(l01, l23);
        }
    }
}

// ---------------------------------------------------------------------------
// Flash attention: R8 tiling (64-q-tile, 4 warps x 16 rows, 128 threads)
// + bitmask adjacency + no-max softmax (both validated in R9).
// ---------------------------------------------------------------------------
#define SW_Q_HI 0
#define SW_Q_LO 2304
#define SW_K_HI 4608
#define SW_K_LO 6912
#define SW_V_HI 9216
#define SW_V_LO 11520
#define ATTN_SMEM_BYTES (13824 * 4)

__global__ __launch_bounds__(128)
void attn_mma_kernel() {
    extern __shared__ unsigned smw[];

    const int qt = blockIdx.x;
    const int h  = blockIdx.y;
    const int b  = blockIdx.z;
    const int tid  = threadIdx.x;
    const int wid  = tid >> 5;
    const int lane = tid & 31;
    const int qbase = qt * 64;
    const int wr0 = wid * 16;
    const int qr = lane >> 2;
    const int qc = lane & 3;

    // ---- load Q tile (hi/lo) ----
    for (int t = tid; t < 512; t += 128) {
        int r = t >> 3, s = t & 7;
        size_t g = (size_t)(b * NTOK + qbase + r) * DM + h * HD + s * 8;
        *(uint4*)&smw[SW_Q_HI + r * 36 + s * 4] = *(const uint4*)(g_qhi + g);
        *(uint4*)&smw[SW_Q_LO + r * 36 + s * 4] = *(const uint4*)(g_qlo + g);
    }

    float oacc[8][4];
    #pragma unroll
    for (int nt = 0; nt < 8; nt++)
        #pragma unroll
        for (int j = 0; j < 4; j++) oacc[nt][j] = 0.0f;

    float lA = 0.0f, lB = 0.0f;
    const int rowA = qbase + wr0 + qr;      // absolute q row (A half)
    const unsigned long long* bitsA = g_adjbits + (size_t)rowA * 32;
    const unsigned long long* bitsB = bitsA + (size_t)8 * 32;

    for (int kt = 0; kt < NTOK / 64; kt++) {
        const int kbase = kt * 64;
        __syncthreads();
        for (int t = tid; t < 512; t += 128) {
            int r = t >> 3, s = t & 7;
            size_t gk = (size_t)(b * NTOK + kbase + r) * DM + h * HD + s * 8;
            *(uint4*)&smw[SW_K_HI + r * 36 + s * 4] = *(const uint4*)(g_khi + gk);
            *(uint4*)&smw[SW_K_LO + r * 36 + s * 4] = *(const uint4*)(g_klo + gk);
            size_t gv = ((size_t)((b * NH + h) * HD + r)) * NTOK + kbase + s * 8;
            *(uint4*)&smw[SW_V_HI + r * 36 + s * 4] = *(const uint4*)(g_vthi + gv);
            *(uint4*)&smw[SW_V_LO + r * 36 + s * 4] = *(const uint4*)(g_vtlo + gv);
        }
        __syncthreads();

        // ---- S = Q @ K^T ----
        float s_[8][4];
        #pragma unroll
        for (int nt = 0; nt < 8; nt++)
            #pragma unroll
            for (int j = 0; j < 4; j++) s_[nt][j] = 0.0f;

        #pragma unroll
        for (int kc = 0; kc < 4; kc++) {
            const int abase = (wr0 + qr) * 36 + kc * 8 + qc;
            unsigned ah0 = smw[SW_Q_HI + abase];
            unsigned ah1 = smw[SW_Q_HI + abase + 8 * 36];
            unsigned ah2 = smw[SW_Q_HI + abase + 4];
            unsigned ah3 = smw[SW_Q_HI + abase + 8 * 36 + 4];
            unsigned al0 = smw[SW_Q_LO + abase];
            unsigned al1 = smw[SW_Q_LO + abase + 8 * 36];
            unsigned al2 = smw[SW_Q_LO + abase + 4];
            unsigned al3 = smw[SW_Q_LO + abase + 8 * 36 + 4];
            #pragma unroll
            for (int nt = 0; nt < 8; nt++) {
                const int bbase = (nt * 8 + qr) * 36 + kc * 8 + qc;
                unsigned bh0 = smw[SW_K_HI + bbase];
                unsigned bh1 = smw[SW_K_HI + bbase + 4];
                unsigned bl0 = smw[SW_K_LO + bbase];
                unsigned bl1 = smw[SW_K_LO + bbase + 4];
                mma16816(s_[nt], ah0, ah1, ah2, ah3, bh0, bh1);
                mma16816(s_[nt], ah0, ah1, ah2, ah3, bl0, bl1);
                mma16816(s_[nt], al0, al1, al2, al3, bh0, bh1);
            }
        }

        // ---- no-max softmax: P = expf(s/8) * maskbit ----
        {
            unsigned long long bA = bitsA[kt];
            unsigned long long bB = bitsB[kt];
            #pragma unroll
            for (int nt = 0; nt < 8; nt++) {
                int sh = nt * 8 + qc * 2;
                float mA0 = (float)((bA >> sh) & 1ull);
                float mA1 = (float)((bA >> (sh + 1)) & 1ull);
                float mB0 = (float)((bB >> sh) & 1ull);
                float mB1 = (float)((bB >> (sh + 1)) & 1ull);
                s_[nt][0] = __expf(s_[nt][0] * 0.125f) * mA0;
                s_[nt][1] = __expf(s_[nt][1] * 0.125f) * mA1;
                s_[nt][2] = __expf(s_[nt][2] * 0.125f) * mB0;
                s_[nt][3] = __expf(s_[nt][3] * 0.125f) * mB1;
                lA += s_[nt][0] + s_[nt][1];
                lB += s_[nt][2] + s_[nt][3];
            }
        }

        // ---- O += P @ V ----
        #pragma unroll
        for (int kc = 0; kc < 4; kc++) {
            const int n0 = 2 * kc, n1 = 2 * kc + 1;
            unsigned ph0, pl0, ph1, pl1, ph2, pl2, ph3, pl3;
            split2(s_[n0][0], s_[n0][1], ph0, pl0);
            split2(s_[n0][2], s_[n0][3], ph1, pl1);
            split2(s_[n1][0], s_[n1][1], ph2, pl2);
            split2(s_[n1][2], s_[n1][3], ph3, pl3);
            #pragma unroll
            for (int nt = 0; nt < 8; nt++) {
                const int bbase = (nt * 8 + qr) * 36 + kc * 8 + qc;
                unsigned bh0 = smw[SW_V_HI + bbase];
                unsigned bh1 = smw[SW_V_HI + bbase + 4];
                unsigned bl0 = smw[SW_V_LO + bbase];
                unsigned bl1 = smw[SW_V_LO + bbase + 4];
                mma16816(oacc[nt], ph0, ph1, ph2, ph3, bh0, bh1);
                mma16816(oacc[nt], ph0, ph1, ph2, ph3, bl0, bl1);
                mma16816(oacc[nt], pl0, pl1, pl2, pl3, bh0, bh1);
            }
        }
    }

    // ---- epilogue: reduce l across the 4 qc lanes, normalize, split-store ----
    lA += __shfl_xor_sync(0xffffffffu, lA, 1);
    lA += __shfl_xor_sync(0xffffffffu, lA, 2);
    lB += __shfl_xor_sync(0xffffffffu, lB, 1);
    lB += __shfl_xor_sync(0xffffffffu, lB, 2);
    float invA = 1.0f / lA;
    float invB = 1.0f / lB;
    size_t offA = (size_t)(b * NTOK + rowA) * DM + h * HD;
    size_t offB = offA + (size_t)8 * DM;
    #pragma unroll
    for (int nt = 0; nt < 8; nt++) {
        int col = nt * 8 + qc * 2;
        unsigned hA, lAv, hB, lBv;
        split2(oacc[nt][0] * invA, oacc[nt][1] * invA, hA, lAv);
        split2(oacc[nt][2] * invB, oacc[nt][3] * invB, hB, lBv);
        *(unsigned*)(g_aohi + offA + col) = hA;
        *(unsigned*)(g_aolo + offA + col) = lAv;
        *(unsigned*)(g_aohi + offB + col) = hB;
        *(unsigned*)(g_aolo + offB + col) = lBv;
    }
}

// ---------------------------------------------------------------------------
extern "C" void kernel_launch(void* const* d_in, const int* in_sizes, int n_in,
                              void* d_out, int out_size) {
    const float* x   = (const float*)d_in[0];
    const float* adj = (const float*)d_in[1];
    const float* Wq  = (const float*)d_in[2];
    const float* bq  = (const float*)d_in[3];
    const float* Wk  = (const float*)d_in[4];
    const float* bk  = (const float*)d_in[5];
    const float* Wv  = (const float*)d_in[6];
    const float* bv  = (const float*)d_in[7];
    const float* Wo  = (const float*)d_in[8];
    const float* bo  = (const float*)d_in[9];
    float* out = (float*)d_out;

    unsigned short *xhi, *xlo, *qhi, *qlo, *khi, *klo, *vthi, *vtlo, *aohi, *aolo, *wthi, *wtlo;
    cudaGetSymbolAddress((void**)&xhi,  g_xhi);
    cudaGetSymbolAddress((void**)&xlo,  g_xlo);
    cudaGetSymbolAddress((void**)&qhi,  g_qhi);
    cudaGetSymbolAddress((void**)&qlo,  g_qlo);
    cudaGetSymbolAddress((void**)&khi,  g_khi);
    cudaGetSymbolAddress((void**)&klo,  g_klo);
    cudaGetSymbolAddress((void**)&vthi, g_vthi);
    cudaGetSymbolAddress((void**)&vtlo, g_vtlo);
    cudaGetSymbolAddress((void**)&aohi, g_aohi);
    cudaGetSymbolAddress((void**)&aolo, g_aolo);
    cudaGetSymbolAddress((void**)&wthi, g_wthi);
    cudaGetSymbolAddress((void**)&wtlo, g_wtlo);

    // 1) split inputs / weights / pack mask
    split_x_kernel<<<(MROWS * DM) / (256 * 4), 256>>>(x);
    dim3 wg(DM / 32, DM / 32);
    split_wT_kernel<<<wg, 256>>>(Wq, 0);
    split_wT_kernel<<<wg, 256>>>(Wk, 1);
    split_wT_kernel<<<wg, 256>>>(Wv, 2);
    split_wT_kernel<<<wg, 256>>>(Wo, 3);
    pack_adj_kernel<<<(NTOK * (NTOK / 64)) / 8, 256>>>(adj);

    // 2) projection GEMMs
    cudaFuncSetAttribute(mma_gemm_kernel<0>, cudaFuncAttributeMaxDynamicSharedMemorySize, GEMM_SMEM_BYTES);
    cudaFuncSetAttribute(mma_gemm_kernel<1>, cudaFuncAttributeMaxDynamicSharedMemorySize, GEMM_SMEM_BYTES);
    cudaFuncSetAttribute(mma_gemm_kernel<2>, cudaFuncAttributeMaxDynamicSharedMemorySize, GEMM_SMEM_BYTES);
    dim3 gg(DM / 64, MROWS / 128);
    mma_gemm_kernel<1><<<gg, 256, GEMM_SMEM_BYTES>>>(xhi, xlo, wthi + 0 * DM * DM, wtlo + 0 * DM * DM,
                                                     bq, nullptr, qhi, qlo);
    mma_gemm_kernel<1><<<gg, 256, GEMM_SMEM_BYTES>>>(xhi, xlo, wthi + 1 * DM * DM, wtlo + 1 * DM * DM,
                                                     bk, nullptr, khi, klo);
    mma_gemm_kernel<2><<<gg, 256, GEMM_SMEM_BYTES>>>(xhi, xlo, wthi + 2 * DM * DM, wtlo + 2 * DM * DM,
                                                     bv, nullptr, vthi, vtlo);

    // 3) attention
    cudaFuncSetAttribute(attn_mma_kernel, cudaFuncAttributeMaxDynamicSharedMemorySize, ATTN_SMEM_BYTES);
    attn_mma_kernel<<<dim3(NTOK / 64, NH, BATCH), 128, ATTN_SMEM_BYTES>>>();

    // 4) output projection
    mma_gemm_kernel<0><<<gg, 256, GEMM_SMEM_BYTES>>>(aohi, aolo, wthi + 3 * DM * DM, wtlo + 3 * DM * DM,
                                                     bo, out, nullptr, nullptr);
}